// round 14
// baseline (speedup 1.0000x reference)
#include <cuda_runtime.h>

#define N_NODES 50000
#define N_EDGES 500000
#define HID 128
#define EDIM 32
#define KTOT (2 * HID + EDIM)   // 288
#define S2STR 132               // enc smem row stride (132 % 32 = 4)
#define CSTR 164                // cls smem row stride (164 % 32 = 4)
#define GNODES 16               // gru nodes per block

typedef unsigned long long u64;

// ---------------- scratch (device globals: no allocation allowed) ----------------
__device__ float    g_sum [N_NODES * HID];
__device__ float    g_cnt [N_NODES];
__device__ float    g_hnew[N_NODES * HID];
__device__ unsigned g_wtf [KTOT * HID];       // Wc1 tf32
__device__ unsigned g_w1tf[EDIM * HID];       // W1  tf32
__device__ unsigned g_w2tf[HID * HID];        // W2  tf32
__device__ u64      g_wihT4[32 * 384 * 2];    // Wih transposed+interleaved
__device__ u64      g_whhT4[32 * 384 * 2];    // Whh transposed+interleaved

// ---------------- zero scratch ----------------
__global__ void zero_k() {
    int i = blockIdx.x * blockDim.x + threadIdx.x;
    if (i < N_NODES * HID) g_sum[i] = 0.0f;
    if (i < N_NODES)       g_cnt[i] = 0.0f;
}

// ---------------- tf32 helpers ----------------
__device__ __forceinline__ unsigned f2tf(float x) {
    unsigned r;
    asm("cvt.rna.tf32.f32 %0, %1;" : "=r"(r) : "f"(x));
    return r;
}
__device__ __forceinline__ float tf32f(float x) { return __uint_as_float(f2tf(x)); }

__global__ void prep_all_k(const float* __restrict__ Wc1,
                           const float* __restrict__ W1,
                           const float* __restrict__ W2) {
    int i = blockIdx.x * blockDim.x + threadIdx.x;
    if (i < KTOT * HID) g_wtf [i] = f2tf(Wc1[i]);
    if (i < EDIM * HID) g_w1tf[i] = f2tf(W1[i]);
    if (i < HID  * HID) g_w2tf[i] = f2tf(W2[i]);
}

__device__ __forceinline__ u64 pk2(float lo, float hi) {
    return ((u64)__float_as_uint(hi) << 32) | (u64)__float_as_uint(lo);
}

__global__ void prep_gru_k(const float* __restrict__ Wih, const float* __restrict__ Whh) {
    int i = blockIdx.x * blockDim.x + threadIdx.x;
    if (i < 32 * 384) {
        int k4 = i / 384, j = i - k4 * 384;
        const float* wi = Wih + (long)j * HID + k4 * 4;
        const float* wh = Whh + (long)j * HID + k4 * 4;
        g_wihT4[i * 2]     = pk2(wi[0], wi[1]);
        g_wihT4[i * 2 + 1] = pk2(wi[2], wi[3]);
        g_whhT4[i * 2]     = pk2(wh[0], wh[1]);
        g_whhT4[i * 2 + 1] = pk2(wh[2], wh[3]);
    }
}

__device__ __forceinline__ void mma_tf32(float* d,
                                         unsigned a0, unsigned a1, unsigned a2, unsigned a3,
                                         unsigned b0, unsigned b1) {
    asm("mma.sync.aligned.m16n8k8.row.col.f32.tf32.tf32.f32 "
        "{%0,%1,%2,%3}, {%4,%5,%6,%7}, {%8,%9}, {%0,%1,%2,%3};"
        : "+f"(d[0]), "+f"(d[1]), "+f"(d[2]), "+f"(d[3])
        : "r"(a0), "r"(a1), "r"(a2), "r"(a3), "r"(b0), "r"(b1));
}

// ---------------- packed fp32x2 helpers (FFMA2, gru) ----------------
__device__ __forceinline__ u64 fma2(u64 a, u64 b, u64 c) {
    u64 d;
    asm("fma.rn.f32x2 %0, %1, %2, %3;" : "=l"(d) : "l"(a), "l"(b), "l"(c));
    return d;
}
__device__ __forceinline__ void unpack2(u64 v, float& lo, float& hi) {
    asm("mov.b64 {%0, %1}, %2;" : "=f"(lo), "=f"(hi) : "l"(v));
}
__device__ __forceinline__ float4 ldg4(const float* p) { return __ldg((const float4*)p); }

// ---------------- kernel 1: edge encoder via tf32 MMA, single-buffer, reg-LN ------
__global__ void __launch_bounds__(128, 4) enc_mma_k(
    const float* __restrict__ ea, const int* __restrict__ eidx,
    const float* __restrict__ b1, const float* __restrict__ g1,
    const float* __restrict__ be1,
    const float* __restrict__ b2, const float* __restrict__ g2,
    const float* __restrict__ be2)
{
    __shared__ float buf[64 * S2STR];
    __shared__ float st1[64 * 2];
    __shared__ float st2[64 * 2];
    __shared__ int   sidx[64];

    const int tid  = threadIdx.x;
    const int w    = tid >> 5;
    const int lane = tid & 31;
    const int l4   = lane >> 2;
    const int lm   = lane & 3;
    const long base = (long)blockIdx.x * 64;
    const int nw   = w * 32;

    if (tid < 64) {
        st1[tid * 2] = 0.f; st1[tid * 2 + 1] = 0.f;
        st2[tid * 2] = 0.f; st2[tid * 2 + 1] = 0.f;
        long eg = base + tid;
        sidx[tid] = (eg < N_EDGES) ? eidx[eg] : -1;
    }
    for (int idx = tid; idx < 64 * 8; idx += 128) {
        int e = idx >> 3, q = idx & 7;
        long eg = base + e;
        float4 v = make_float4(0.f, 0.f, 0.f, 0.f);
        if (eg < N_EDGES) v = ldg4(ea + eg * EDIM + q * 4);
        float4 t = make_float4(tf32f(v.x), tf32f(v.y), tf32f(v.z), tf32f(v.w));
        *(float4*)&buf[e * S2STR + q * 4] = t;
    }
    __syncthreads();

    float acc[4][4][4];

#pragma unroll
    for (int mt = 0; mt < 4; ++mt)
#pragma unroll
        for (int nt = 0; nt < 4; ++nt)
#pragma unroll
            for (int i = 0; i < 4; ++i) acc[mt][nt][i] = 0.0f;

#pragma unroll
    for (int ks = 0; ks < 4; ++ks) {
        const int k0 = ks * 8;
        unsigned a[4][4];
#pragma unroll
        for (int mt = 0; mt < 4; ++mt) {
            const float* rp = buf + (mt * 16 + l4) * S2STR + k0 + lm;
            a[mt][0] = __float_as_uint(rp[0]);
            a[mt][1] = __float_as_uint(rp[8 * S2STR]);
            a[mt][2] = __float_as_uint(rp[4]);
            a[mt][3] = __float_as_uint(rp[8 * S2STR + 4]);
        }
#pragma unroll
        for (int nt = 0; nt < 4; ++nt) {
            int n = nw + nt * 8 + l4;
            unsigned bb0 = __ldg(g_w1tf + (k0 + lm) * HID + n);
            unsigned bb1 = __ldg(g_w1tf + (k0 + lm + 4) * HID + n);
#pragma unroll
            for (int mt = 0; mt < 4; ++mt)
                mma_tf32(acc[mt][nt], a[mt][0], a[mt][1], a[mt][2], a[mt][3], bb0, bb1);
        }
    }
    __syncthreads();

    {
        float bv0[4], bv1[4];
#pragma unroll
        for (int nt = 0; nt < 4; ++nt) {
            int c = nw + nt * 8 + lm * 2;
            bv0[nt] = __ldg(b1 + c); bv1[nt] = __ldg(b1 + c + 1);
        }
#pragma unroll
        for (int mt = 0; mt < 4; ++mt) {
            float s0 = 0.f, q0 = 0.f, s1 = 0.f, q1 = 0.f;
#pragma unroll
            for (int nt = 0; nt < 4; ++nt) {
                acc[mt][nt][0] += bv0[nt]; acc[mt][nt][1] += bv1[nt];
                acc[mt][nt][2] += bv0[nt]; acc[mt][nt][3] += bv1[nt];
                s0 += acc[mt][nt][0] + acc[mt][nt][1];
                q0 += acc[mt][nt][0] * acc[mt][nt][0] + acc[mt][nt][1] * acc[mt][nt][1];
                s1 += acc[mt][nt][2] + acc[mt][nt][3];
                q1 += acc[mt][nt][2] * acc[mt][nt][2] + acc[mt][nt][3] * acc[mt][nt][3];
            }
            s0 += __shfl_xor_sync(0xffffffffu, s0, 1); s0 += __shfl_xor_sync(0xffffffffu, s0, 2);
            q0 += __shfl_xor_sync(0xffffffffu, q0, 1); q0 += __shfl_xor_sync(0xffffffffu, q0, 2);
            s1 += __shfl_xor_sync(0xffffffffu, s1, 1); s1 += __shfl_xor_sync(0xffffffffu, s1, 2);
            q1 += __shfl_xor_sync(0xffffffffu, q1, 1); q1 += __shfl_xor_sync(0xffffffffu, q1, 2);
            if (lm == 0) {
                int r0 = mt * 16 + l4;
                atomicAdd(&st1[r0 * 2],  s0); atomicAdd(&st1[r0 * 2 + 1],  q0);
                atomicAdd(&st1[(r0 + 8) * 2], s1); atomicAdd(&st1[(r0 + 8) * 2 + 1], q1);
            }
        }
    }
    __syncthreads();

    {
        float gv0[4], gv1[4], ev0[4], ev1[4];
#pragma unroll
        for (int nt = 0; nt < 4; ++nt) {
            int c = nw + nt * 8 + lm * 2;
            gv0[nt] = __ldg(g1 + c);  gv1[nt] = __ldg(g1 + c + 1);
            ev0[nt] = __ldg(be1 + c); ev1[nt] = __ldg(be1 + c + 1);
        }
#pragma unroll
        for (int mt = 0; mt < 4; ++mt) {
            int r0 = mt * 16 + l4, r1 = r0 + 8;
            float mu0 = st1[r0 * 2] * (1.0f / 128.0f);
            float va0 = st1[r0 * 2 + 1] * (1.0f / 128.0f) - mu0 * mu0;
            float rs0 = rsqrtf(va0 + 1e-5f);
            float mu1 = st1[r1 * 2] * (1.0f / 128.0f);
            float va1 = st1[r1 * 2 + 1] * (1.0f / 128.0f) - mu1 * mu1;
            float rs1 = rsqrtf(va1 + 1e-5f);
#pragma unroll
            for (int nt = 0; nt < 4; ++nt) {
                int c = nw + nt * 8 + lm * 2;
                buf[r0 * S2STR + c]     = tf32f(fmaxf((acc[mt][nt][0] - mu0) * rs0 * gv0[nt] + ev0[nt], 0.f));
                buf[r0 * S2STR + c + 1] = tf32f(fmaxf((acc[mt][nt][1] - mu0) * rs0 * gv1[nt] + ev1[nt], 0.f));
                buf[r1 * S2STR + c]     = tf32f(fmaxf((acc[mt][nt][2] - mu1) * rs1 * gv0[nt] + ev0[nt], 0.f));
                buf[r1 * S2STR + c + 1] = tf32f(fmaxf((acc[mt][nt][3] - mu1) * rs1 * gv1[nt] + ev1[nt], 0.f));
            }
        }
    }
    __syncthreads();

#pragma unroll
    for (int mt = 0; mt < 4; ++mt)
#pragma unroll
        for (int nt = 0; nt < 4; ++nt)
#pragma unroll
            for (int i = 0; i < 4; ++i) acc[mt][nt][i] = 0.0f;

#pragma unroll 4
    for (int ks = 0; ks < 16; ++ks) {
        const int k0 = ks * 8;
        unsigned a[4][4];
#pragma unroll
        for (int mt = 0; mt < 4; ++mt) {
            const float* rp = buf + (mt * 16 + l4) * S2STR + k0 + lm;
            a[mt][0] = __float_as_uint(rp[0]);
            a[mt][1] = __float_as_uint(rp[8 * S2STR]);
            a[mt][2] = __float_as_uint(rp[4]);
            a[mt][3] = __float_as_uint(rp[8 * S2STR + 4]);
        }
#pragma unroll
        for (int nt = 0; nt < 4; ++nt) {
            int n = nw + nt * 8 + l4;
            unsigned bb0 = __ldg(g_w2tf + (k0 + lm) * HID + n);
            unsigned bb1 = __ldg(g_w2tf + (k0 + lm + 4) * HID + n);
#pragma unroll
            for (int mt = 0; mt < 4; ++mt)
                mma_tf32(acc[mt][nt], a[mt][0], a[mt][1], a[mt][2], a[mt][3], bb0, bb1);
        }
    }

    {
        float bv0[4], bv1[4];
#pragma unroll
        for (int nt = 0; nt < 4; ++nt) {
            int c = nw + nt * 8 + lm * 2;
            bv0[nt] = __ldg(b2 + c); bv1[nt] = __ldg(b2 + c + 1);
        }
#pragma unroll
        for (int mt = 0; mt < 4; ++mt) {
            float s0 = 0.f, q0 = 0.f, s1 = 0.f, q1 = 0.f;
#pragma unroll
            for (int nt = 0; nt < 4; ++nt) {
                acc[mt][nt][0] += bv0[nt]; acc[mt][nt][1] += bv1[nt];
                acc[mt][nt][2] += bv0[nt]; acc[mt][nt][3] += bv1[nt];
                s0 += acc[mt][nt][0] + acc[mt][nt][1];
                q0 += acc[mt][nt][0] * acc[mt][nt][0] + acc[mt][nt][1] * acc[mt][nt][1];
                s1 += acc[mt][nt][2] + acc[mt][nt][3];
                q1 += acc[mt][nt][2] * acc[mt][nt][2] + acc[mt][nt][3] * acc[mt][nt][3];
            }
            s0 += __shfl_xor_sync(0xffffffffu, s0, 1); s0 += __shfl_xor_sync(0xffffffffu, s0, 2);
            q0 += __shfl_xor_sync(0xffffffffu, q0, 1); q0 += __shfl_xor_sync(0xffffffffu, q0, 2);
            s1 += __shfl_xor_sync(0xffffffffu, s1, 1); s1 += __shfl_xor_sync(0xffffffffu, s1, 2);
            q1 += __shfl_xor_sync(0xffffffffu, q1, 1); q1 += __shfl_xor_sync(0xffffffffu, q1, 2);
            if (lm == 0) {
                int r0 = mt * 16 + l4;
                atomicAdd(&st2[r0 * 2],  s0); atomicAdd(&st2[r0 * 2 + 1],  q0);
                atomicAdd(&st2[(r0 + 8) * 2], s1); atomicAdd(&st2[(r0 + 8) * 2 + 1], q1);
            }
        }
    }
    __syncthreads();

    {
        float gv0[4], gv1[4], ev0[4], ev1[4];
#pragma unroll
        for (int nt = 0; nt < 4; ++nt) {
            int c = nw + nt * 8 + lm * 2;
            gv0[nt] = __ldg(g2 + c);  gv1[nt] = __ldg(g2 + c + 1);
            ev0[nt] = __ldg(be2 + c); ev1[nt] = __ldg(be2 + c + 1);
        }
#pragma unroll
        for (int mt = 0; mt < 4; ++mt) {
            int r0 = mt * 16 + l4, r1 = r0 + 8;
            float mu0 = st2[r0 * 2] * (1.0f / 128.0f);
            float va0 = st2[r0 * 2 + 1] * (1.0f / 128.0f) - mu0 * mu0;
            float rs0 = rsqrtf(va0 + 1e-5f);
            float mu1 = st2[r1 * 2] * (1.0f / 128.0f);
            float va1 = st2[r1 * 2 + 1] * (1.0f / 128.0f) - mu1 * mu1;
            float rs1 = rsqrtf(va1 + 1e-5f);
            int s0i = sidx[r0], s1i = sidx[r1];
#pragma unroll
            for (int nt = 0; nt < 4; ++nt) {
                int c = nw + nt * 8 + lm * 2;
                if (s0i >= 0) {
                    float* dp = g_sum + (long)s0i * HID + c;
                    atomicAdd(dp,     fmaxf((acc[mt][nt][0] - mu0) * rs0 * gv0[nt] + ev0[nt], 0.f));
                    atomicAdd(dp + 1, fmaxf((acc[mt][nt][1] - mu0) * rs0 * gv1[nt] + ev1[nt], 0.f));
                }
                if (s1i >= 0) {
                    float* dp = g_sum + (long)s1i * HID + c;
                    atomicAdd(dp,     fmaxf((acc[mt][nt][2] - mu1) * rs1 * gv0[nt] + ev0[nt], 0.f));
                    atomicAdd(dp + 1, fmaxf((acc[mt][nt][3] - mu1) * rs1 * gv1[nt] + ev1[nt], 0.f));
                }
            }
        }
    }
    if (tid < 64 && sidx[tid] >= 0) atomicAdd(&g_cnt[sidx[tid]], 1.0f);
}

// ---------------- kernel 2: mean + GRUCell (16 nodes/block — weight reuse x2) -----
__global__ void __launch_bounds__(384) gru_k(
    const float* __restrict__ hprev,
    const float* __restrict__ bih, const float* __restrict__ bhh)
{
    __shared__ float sA[GNODES][HID];
    __shared__ float sH[GNODES][HID];
    __shared__ float sR[GNODES][HID];
    __shared__ float sZ[GNODES][HID];

    const int tid = threadIdx.x;
    const long node0 = (long)blockIdx.x * GNODES;

    for (int idx = tid; idx < GNODES * HID; idx += 384) {
        int n = idx >> 7, k = idx & 127;
        long g = (node0 + n) * HID + k;
        float c = g_cnt[node0 + n];
        sA[n][k] = g_sum[g] / fmaxf(c, 1.0f);
        sH[n][k] = hprev[g];
    }
    __syncthreads();

    const int j = tid;
    u64 gx2[GNODES], gh2[GNODES];
#pragma unroll
    for (int n = 0; n < GNODES; ++n) { gx2[n] = 0ull; gh2[n] = 0ull; }

    const ulonglong2* wiT = (const ulonglong2*)g_wihT4;
    const ulonglong2* whT = (const ulonglong2*)g_whhT4;
#pragma unroll 2
    for (int k4 = 0; k4 < HID / 4; ++k4) {
        ulonglong2 wi2 = __ldg(wiT + k4 * 384 + j);
        ulonglong2 wh2 = __ldg(whT + k4 * 384 + j);
#pragma unroll
        for (int n = 0; n < GNODES; ++n) {
            ulonglong2 a2 = *(const ulonglong2*)&sA[n][k4 * 4];
            ulonglong2 h2 = *(const ulonglong2*)&sH[n][k4 * 4];
            gx2[n] = fma2(a2.x, wi2.x, gx2[n]);
            gx2[n] = fma2(a2.y, wi2.y, gx2[n]);
            gh2[n] = fma2(h2.x, wh2.x, gh2[n]);
            gh2[n] = fma2(h2.y, wh2.y, gh2[n]);
        }
    }

    float gx[GNODES], gh[GNODES];
    const float bi = __ldg(bih + j), bh = __ldg(bhh + j);
#pragma unroll
    for (int n = 0; n < GNODES; ++n) {
        float lo, hi;
        unpack2(gx2[n], lo, hi); gx[n] = bi + lo + hi;
        unpack2(gh2[n], lo, hi); gh[n] = bh + lo + hi;
    }

    if (j < HID) {
#pragma unroll
        for (int n = 0; n < GNODES; ++n)
            sR[n][j] = 1.0f / (1.0f + expf(-(gx[n] + gh[n])));
    } else if (j < 2 * HID) {
        int jj = j - HID;
#pragma unroll
        for (int n = 0; n < GNODES; ++n)
            sZ[n][jj] = 1.0f / (1.0f + expf(-(gx[n] + gh[n])));
    }
    __syncthreads();
    if (j >= 2 * HID) {
        int jj = j - 2 * HID;
#pragma unroll
        for (int n = 0; n < GNODES; ++n) {
            float r  = sR[n][jj];
            float nn = tanhf(gx[n] + r * gh[n]);
            float z  = sZ[n][jj];
            g_hnew[(node0 + n) * HID + jj] = (1.0f - z) * nn + z * sH[n][jj];
        }
    }
}

// ---------------- kernel 3: classifier, split-K tf32 mma (unchanged) ------
__global__ void __launch_bounds__(128, 5) cls_k(
    const float* __restrict__ ea, const int* __restrict__ eidx,
    const float* __restrict__ bc1, const float* __restrict__ Wc2,
    const float* __restrict__ bc2, float* __restrict__ out)
{
    __shared__ float buf[64 * CSTR];
    __shared__ float part[64];

    const int tid  = threadIdx.x;
    const int w    = tid >> 5;
    const int lane = tid & 31;
    const int l4   = lane >> 2;
    const int lm   = lane & 3;
    const long base = (long)blockIdx.x * 64;
    const int nw   = w * 32;

    if (tid < 64) part[tid] = 0.0f;

    float acc[4][4][4];
#pragma unroll
    for (int mt = 0; mt < 4; ++mt)
#pragma unroll
        for (int nt = 0; nt < 4; ++nt)
#pragma unroll
            for (int i = 0; i < 4; ++i) acc[mt][nt][i] = 0.0f;

    for (int idx = tid; idx < 64 * 32; idx += 128) {
        int e = idx >> 5, q = idx & 31;
        long eg = base + e;
        float4 v = make_float4(0.f, 0.f, 0.f, 0.f);
        if (eg < N_EDGES) {
            int s = eidx[eg];
            v = ldg4(g_hnew + (long)s * HID + q * 4);
        }
        float4 t = make_float4(tf32f(v.x), tf32f(v.y), tf32f(v.z), tf32f(v.w));
        *(float4*)&buf[e * CSTR + q * 4] = t;
    }
    __syncthreads();

#pragma unroll 4
    for (int ks = 0; ks < 16; ++ks) {
        const int k0 = ks * 8;
        unsigned a[4][4];
#pragma unroll
        for (int mt = 0; mt < 4; ++mt) {
            const float* rp = buf + (mt * 16 + l4) * CSTR + k0 + lm;
            a[mt][0] = __float_as_uint(rp[0]);
            a[mt][1] = __float_as_uint(rp[8 * CSTR]);
            a[mt][2] = __float_as_uint(rp[4]);
            a[mt][3] = __float_as_uint(rp[8 * CSTR + 4]);
        }
#pragma unroll
        for (int nt = 0; nt < 4; ++nt) {
            int n = nw + nt * 8 + l4;
            unsigned b0 = __ldg(g_wtf + (k0 + lm) * HID + n);
            unsigned b1 = __ldg(g_wtf + (k0 + lm + 4) * HID + n);
#pragma unroll
            for (int mt = 0; mt < 4; ++mt)
                mma_tf32(acc[mt][nt], a[mt][0], a[mt][1], a[mt][2], a[mt][3], b0, b1);
        }
    }
    __syncthreads();

    for (int idx = tid; idx < 64 * 40; idx += 128) {
        int e = idx / 40, q = idx - e * 40;
        long eg = base + e;
        float4 v = make_float4(0.f, 0.f, 0.f, 0.f);
        if (eg < N_EDGES) {
            if (q < 32) {
                int d = eidx[N_EDGES + eg];
                v = ldg4(g_hnew + (long)d * HID + q * 4);
            } else {
                v = ldg4(ea + eg * EDIM + (q - 32) * 4);
            }
        }
        float4 t = make_float4(tf32f(v.x), tf32f(v.y), tf32f(v.z), tf32f(v.w));
        *(float4*)&buf[e * CSTR + q * 4] = t;
    }
    __syncthreads();

#pragma unroll 4
    for (int ks = 0; ks < 20; ++ks) {
        const int k0l = ks * 8;
        const int k0g = 128 + ks * 8;
        unsigned a[4][4];
#pragma unroll
        for (int mt = 0; mt < 4; ++mt) {
            const float* rp = buf + (mt * 16 + l4) * CSTR + k0l + lm;
            a[mt][0] = __float_as_uint(rp[0]);
            a[mt][1] = __float_as_uint(rp[8 * CSTR]);
            a[mt][2] = __float_as_uint(rp[4]);
            a[mt][3] = __float_as_uint(rp[8 * CSTR + 4]);
        }
#pragma unroll
        for (int nt = 0; nt < 4; ++nt) {
            int n = nw + nt * 8 + l4;
            unsigned b0 = __ldg(g_wtf + (k0g + lm) * HID + n);
            unsigned b1 = __ldg(g_wtf + (k0g + lm + 4) * HID + n);
#pragma unroll
            for (int mt = 0; mt < 4; ++mt)
                mma_tf32(acc[mt][nt], a[mt][0], a[mt][1], a[mt][2], a[mt][3], b0, b1);
        }
    }

#pragma unroll
    for (int nt = 0; nt < 4; ++nt) {
        int n0 = nw + nt * 8 + lm * 2;
        float bcA = __ldg(bc1 + n0),  bcB = __ldg(bc1 + n0 + 1);
        float w2A = __ldg(Wc2 + n0),  w2B = __ldg(Wc2 + n0 + 1);
#pragma unroll
        for (int mt = 0; mt < 4; ++mt) {
            float vlo = fmaxf(acc[mt][nt][0] + bcA, 0.f) * w2A
                      + fmaxf(acc[mt][nt][1] + bcB, 0.f) * w2B;
            float vhi = fmaxf(acc[mt][nt][2] + bcA, 0.f) * w2A
                      + fmaxf(acc[mt][nt][3] + bcB, 0.f) * w2B;
            vlo += __shfl_xor_sync(0xffffffffu, vlo, 1);
            vlo += __shfl_xor_sync(0xffffffffu, vlo, 2);
            vhi += __shfl_xor_sync(0xffffffffu, vhi, 1);
            vhi += __shfl_xor_sync(0xffffffffu, vhi, 2);
            if (lm == 0) {
                atomicAdd(&part[mt * 16 + l4],     vlo);
                atomicAdd(&part[mt * 16 + l4 + 8], vhi);
            }
        }
    }
    __syncthreads();

    if (tid < 64) {
        long eg = base + tid;
        if (eg < N_EDGES) out[eg] = part[tid] + __ldg(bc2);
    }
}

// ---------------- launch ----------------
extern "C" void kernel_launch(void* const* d_in, const int* in_sizes, int n_in,
                              void* d_out, int out_size)
{
    (void)in_sizes; (void)n_in; (void)out_size;
    const int*   eidx  = (const int*)  d_in[1];
    const float* ea    = (const float*)d_in[2];
    const float* hprev = (const float*)d_in[3];
    const float* W1 = (const float*)d_in[4];
    const float* b1 = (const float*)d_in[5];
    const float* g1 = (const float*)d_in[6];
    const float* be1= (const float*)d_in[7];
    const float* W2 = (const float*)d_in[8];
    const float* b2 = (const float*)d_in[9];
    const float* g2 = (const float*)d_in[10];
    const float* be2= (const float*)d_in[11];
    const float* Wih= (const float*)d_in[12];
    const float* bih= (const float*)d_in[13];
    const float* Whh= (const float*)d_in[14];
    const float* bhh= (const float*)d_in[15];
    const float* Wc1= (const float*)d_in[16];
    const float* bc1= (const float*)d_in[17];
    const float* Wc2= (const float*)d_in[18];
    const float* bc2= (const float*)d_in[19];
    float* out = (float*)d_out;

    const int nblk = (N_EDGES + 63) / 64;
    zero_k<<<(N_NODES * HID + 255) / 256, 256>>>();
    prep_all_k<<<(KTOT * HID + 255) / 256, 256>>>(Wc1, W1, W2);
    prep_gru_k<<<(32 * 384 + 255) / 256, 256>>>(Wih, Whh);
    enc_mma_k<<<nblk, 128>>>(ea, eidx, b1, g1, be1, b2, g2, be2);
    gru_k<<<(N_NODES + GNODES - 1) / GNODES, 384>>>(hprev, bih, bhh);
    cls_k<<<nblk, 128>>>(ea, eidx, bc1, Wc2, bc2, out);
}

// round 15
// speedup vs baseline: 1.2102x; 1.2102x over previous
#include <cuda_runtime.h>

#define N_NODES 50000
#define N_EDGES 500000
#define HID 128
#define EDIM 32
#define KTOT (2 * HID + EDIM)   // 288
#define S2STR 132               // enc smem row stride (132 % 32 = 4)
#define CSTR 164                // cls smem row stride (164 % 32 = 4)
#define GSTR 132                // gru smem row stride

typedef unsigned long long u64;

// ---------------- scratch (device globals: no allocation allowed) ----------------
__device__ float    g_sum [N_NODES * HID];
__device__ float    g_cnt [N_NODES];
__device__ float    g_hnew[N_NODES * HID];
__device__ float    g_gx  [N_NODES * 384];    // GRU input-gate pre-activations
__device__ float    g_gh  [N_NODES * 384];    // GRU hidden-gate pre-activations
__device__ unsigned g_wtf [KTOT * HID];       // Wc1 tf32
__device__ unsigned g_w1tf[EDIM * HID];       // W1  tf32
__device__ unsigned g_w2tf[HID * HID];        // W2  tf32
__device__ unsigned g_wihTtf[HID * 384];      // Wih^T tf32 [k][j]
__device__ unsigned g_whhTtf[HID * 384];      // Whh^T tf32 [k][j]

// ---------------- zero scratch ----------------
__global__ void zero_k() {
    int i = blockIdx.x * blockDim.x + threadIdx.x;
    if (i < N_NODES * HID) g_sum[i] = 0.0f;
    if (i < N_NODES)       g_cnt[i] = 0.0f;
}

// ---------------- tf32 helpers ----------------
__device__ __forceinline__ unsigned f2tf(float x) {
    unsigned r;
    asm("cvt.rna.tf32.f32 %0, %1;" : "=r"(r) : "f"(x));
    return r;
}
__device__ __forceinline__ float tf32f(float x) { return __uint_as_float(f2tf(x)); }

__global__ void prep_all_k(const float* __restrict__ Wc1,
                           const float* __restrict__ W1,
                           const float* __restrict__ W2) {
    int i = blockIdx.x * blockDim.x + threadIdx.x;
    if (i < KTOT * HID) g_wtf [i] = f2tf(Wc1[i]);
    if (i < EDIM * HID) g_w1tf[i] = f2tf(W1[i]);
    if (i < HID  * HID) g_w2tf[i] = f2tf(W2[i]);
}

// transpose GRU weights to [k][j] tf32
__global__ void prep_gruT_k(const float* __restrict__ Wih, const float* __restrict__ Whh) {
    int i = blockIdx.x * blockDim.x + threadIdx.x;   // over 128*384
    if (i < HID * 384) {
        int k = i / 384, j = i - k * 384;
        g_wihTtf[i] = f2tf(Wih[(long)j * HID + k]);
        g_whhTtf[i] = f2tf(Whh[(long)j * HID + k]);
    }
}

__device__ __forceinline__ void mma_tf32(float* d,
                                         unsigned a0, unsigned a1, unsigned a2, unsigned a3,
                                         unsigned b0, unsigned b1) {
    asm("mma.sync.aligned.m16n8k8.row.col.f32.tf32.tf32.f32 "
        "{%0,%1,%2,%3}, {%4,%5,%6,%7}, {%8,%9}, {%0,%1,%2,%3};"
        : "+f"(d[0]), "+f"(d[1]), "+f"(d[2]), "+f"(d[3])
        : "r"(a0), "r"(a1), "r"(a2), "r"(a3), "r"(b0), "r"(b1));
}

__device__ __forceinline__ float4 ldg4(const float* p) { return __ldg((const float4*)p); }

// ---------------- kernel 1: edge encoder via tf32 MMA (unchanged from R12/R13) ----
__global__ void __launch_bounds__(128, 4) enc_mma_k(
    const float* __restrict__ ea, const int* __restrict__ eidx,
    const float* __restrict__ b1, const float* __restrict__ g1,
    const float* __restrict__ be1,
    const float* __restrict__ b2, const float* __restrict__ g2,
    const float* __restrict__ be2)
{
    __shared__ float buf[64 * S2STR];
    __shared__ float st1[64 * 2];
    __shared__ float st2[64 * 2];
    __shared__ int   sidx[64];

    const int tid  = threadIdx.x;
    const int w    = tid >> 5;
    const int lane = tid & 31;
    const int l4   = lane >> 2;
    const int lm   = lane & 3;
    const long base = (long)blockIdx.x * 64;
    const int nw   = w * 32;

    if (tid < 64) {
        st1[tid * 2] = 0.f; st1[tid * 2 + 1] = 0.f;
        st2[tid * 2] = 0.f; st2[tid * 2 + 1] = 0.f;
        long eg = base + tid;
        sidx[tid] = (eg < N_EDGES) ? eidx[eg] : -1;
    }
    for (int idx = tid; idx < 64 * 8; idx += 128) {
        int e = idx >> 3, q = idx & 7;
        long eg = base + e;
        float4 v = make_float4(0.f, 0.f, 0.f, 0.f);
        if (eg < N_EDGES) v = ldg4(ea + eg * EDIM + q * 4);
        float4 t = make_float4(tf32f(v.x), tf32f(v.y), tf32f(v.z), tf32f(v.w));
        *(float4*)&buf[e * S2STR + q * 4] = t;
    }
    __syncthreads();

    float acc[4][4][4];
#pragma unroll
    for (int mt = 0; mt < 4; ++mt)
#pragma unroll
        for (int nt = 0; nt < 4; ++nt)
#pragma unroll
            for (int i = 0; i < 4; ++i) acc[mt][nt][i] = 0.0f;

#pragma unroll
    for (int ks = 0; ks < 4; ++ks) {
        const int k0 = ks * 8;
        unsigned a[4][4];
#pragma unroll
        for (int mt = 0; mt < 4; ++mt) {
            const float* rp = buf + (mt * 16 + l4) * S2STR + k0 + lm;
            a[mt][0] = __float_as_uint(rp[0]);
            a[mt][1] = __float_as_uint(rp[8 * S2STR]);
            a[mt][2] = __float_as_uint(rp[4]);
            a[mt][3] = __float_as_uint(rp[8 * S2STR + 4]);
        }
#pragma unroll
        for (int nt = 0; nt < 4; ++nt) {
            int n = nw + nt * 8 + l4;
            unsigned bb0 = __ldg(g_w1tf + (k0 + lm) * HID + n);
            unsigned bb1 = __ldg(g_w1tf + (k0 + lm + 4) * HID + n);
#pragma unroll
            for (int mt = 0; mt < 4; ++mt)
                mma_tf32(acc[mt][nt], a[mt][0], a[mt][1], a[mt][2], a[mt][3], bb0, bb1);
        }
    }
    __syncthreads();

    {
        float bv0[4], bv1[4];
#pragma unroll
        for (int nt = 0; nt < 4; ++nt) {
            int c = nw + nt * 8 + lm * 2;
            bv0[nt] = __ldg(b1 + c); bv1[nt] = __ldg(b1 + c + 1);
        }
#pragma unroll
        for (int mt = 0; mt < 4; ++mt) {
            float s0 = 0.f, q0 = 0.f, s1 = 0.f, q1 = 0.f;
#pragma unroll
            for (int nt = 0; nt < 4; ++nt) {
                acc[mt][nt][0] += bv0[nt]; acc[mt][nt][1] += bv1[nt];
                acc[mt][nt][2] += bv0[nt]; acc[mt][nt][3] += bv1[nt];
                s0 += acc[mt][nt][0] + acc[mt][nt][1];
                q0 += acc[mt][nt][0] * acc[mt][nt][0] + acc[mt][nt][1] * acc[mt][nt][1];
                s1 += acc[mt][nt][2] + acc[mt][nt][3];
                q1 += acc[mt][nt][2] * acc[mt][nt][2] + acc[mt][nt][3] * acc[mt][nt][3];
            }
            s0 += __shfl_xor_sync(0xffffffffu, s0, 1); s0 += __shfl_xor_sync(0xffffffffu, s0, 2);
            q0 += __shfl_xor_sync(0xffffffffu, q0, 1); q0 += __shfl_xor_sync(0xffffffffu, q0, 2);
            s1 += __shfl_xor_sync(0xffffffffu, s1, 1); s1 += __shfl_xor_sync(0xffffffffu, s1, 2);
            q1 += __shfl_xor_sync(0xffffffffu, q1, 1); q1 += __shfl_xor_sync(0xffffffffu, q1, 2);
            if (lm == 0) {
                int r0 = mt * 16 + l4;
                atomicAdd(&st1[r0 * 2],  s0); atomicAdd(&st1[r0 * 2 + 1],  q0);
                atomicAdd(&st1[(r0 + 8) * 2], s1); atomicAdd(&st1[(r0 + 8) * 2 + 1], q1);
            }
        }
    }
    __syncthreads();

    {
        float gv0[4], gv1[4], ev0[4], ev1[4];
#pragma unroll
        for (int nt = 0; nt < 4; ++nt) {
            int c = nw + nt * 8 + lm * 2;
            gv0[nt] = __ldg(g1 + c);  gv1[nt] = __ldg(g1 + c + 1);
            ev0[nt] = __ldg(be1 + c); ev1[nt] = __ldg(be1 + c + 1);
        }
#pragma unroll
        for (int mt = 0; mt < 4; ++mt) {
            int r0 = mt * 16 + l4, r1 = r0 + 8;
            float mu0 = st1[r0 * 2] * (1.0f / 128.0f);
            float va0 = st1[r0 * 2 + 1] * (1.0f / 128.0f) - mu0 * mu0;
            float rs0 = rsqrtf(va0 + 1e-5f);
            float mu1 = st1[r1 * 2] * (1.0f / 128.0f);
            float va1 = st1[r1 * 2 + 1] * (1.0f / 128.0f) - mu1 * mu1;
            float rs1 = rsqrtf(va1 + 1e-5f);
#pragma unroll
            for (int nt = 0; nt < 4; ++nt) {
                int c = nw + nt * 8 + lm * 2;
                buf[r0 * S2STR + c]     = tf32f(fmaxf((acc[mt][nt][0] - mu0) * rs0 * gv0[nt] + ev0[nt], 0.f));
                buf[r0 * S2STR + c + 1] = tf32f(fmaxf((acc[mt][nt][1] - mu0) * rs0 * gv1[nt] + ev1[nt], 0.f));
                buf[r1 * S2STR + c]     = tf32f(fmaxf((acc[mt][nt][2] - mu1) * rs1 * gv0[nt] + ev0[nt], 0.f));
                buf[r1 * S2STR + c + 1] = tf32f(fmaxf((acc[mt][nt][3] - mu1) * rs1 * gv1[nt] + ev1[nt], 0.f));
            }
        }
    }
    __syncthreads();

#pragma unroll
    for (int mt = 0; mt < 4; ++mt)
#pragma unroll
        for (int nt = 0; nt < 4; ++nt)
#pragma unroll
            for (int i = 0; i < 4; ++i) acc[mt][nt][i] = 0.0f;

#pragma unroll 4
    for (int ks = 0; ks < 16; ++ks) {
        const int k0 = ks * 8;
        unsigned a[4][4];
#pragma unroll
        for (int mt = 0; mt < 4; ++mt) {
            const float* rp = buf + (mt * 16 + l4) * S2STR + k0 + lm;
            a[mt][0] = __float_as_uint(rp[0]);
            a[mt][1] = __float_as_uint(rp[8 * S2STR]);
            a[mt][2] = __float_as_uint(rp[4]);
            a[mt][3] = __float_as_uint(rp[8 * S2STR + 4]);
        }
#pragma unroll
        for (int nt = 0; nt < 4; ++nt) {
            int n = nw + nt * 8 + l4;
            unsigned bb0 = __ldg(g_w2tf + (k0 + lm) * HID + n);
            unsigned bb1 = __ldg(g_w2tf + (k0 + lm + 4) * HID + n);
#pragma unroll
            for (int mt = 0; mt < 4; ++mt)
                mma_tf32(acc[mt][nt], a[mt][0], a[mt][1], a[mt][2], a[mt][3], bb0, bb1);
        }
    }

    {
        float bv0[4], bv1[4];
#pragma unroll
        for (int nt = 0; nt < 4; ++nt) {
            int c = nw + nt * 8 + lm * 2;
            bv0[nt] = __ldg(b2 + c); bv1[nt] = __ldg(b2 + c + 1);
        }
#pragma unroll
        for (int mt = 0; mt < 4; ++mt) {
            float s0 = 0.f, q0 = 0.f, s1 = 0.f, q1 = 0.f;
#pragma unroll
            for (int nt = 0; nt < 4; ++nt) {
                acc[mt][nt][0] += bv0[nt]; acc[mt][nt][1] += bv1[nt];
                acc[mt][nt][2] += bv0[nt]; acc[mt][nt][3] += bv1[nt];
                s0 += acc[mt][nt][0] + acc[mt][nt][1];
                q0 += acc[mt][nt][0] * acc[mt][nt][0] + acc[mt][nt][1] * acc[mt][nt][1];
                s1 += acc[mt][nt][2] + acc[mt][nt][3];
                q1 += acc[mt][nt][2] * acc[mt][nt][2] + acc[mt][nt][3] * acc[mt][nt][3];
            }
            s0 += __shfl_xor_sync(0xffffffffu, s0, 1); s0 += __shfl_xor_sync(0xffffffffu, s0, 2);
            q0 += __shfl_xor_sync(0xffffffffu, q0, 1); q0 += __shfl_xor_sync(0xffffffffu, q0, 2);
            s1 += __shfl_xor_sync(0xffffffffu, s1, 1); s1 += __shfl_xor_sync(0xffffffffu, s1, 2);
            q1 += __shfl_xor_sync(0xffffffffu, q1, 1); q1 += __shfl_xor_sync(0xffffffffu, q1, 2);
            if (lm == 0) {
                int r0 = mt * 16 + l4;
                atomicAdd(&st2[r0 * 2],  s0); atomicAdd(&st2[r0 * 2 + 1],  q0);
                atomicAdd(&st2[(r0 + 8) * 2], s1); atomicAdd(&st2[(r0 + 8) * 2 + 1], q1);
            }
        }
    }
    __syncthreads();

    {
        float gv0[4], gv1[4], ev0[4], ev1[4];
#pragma unroll
        for (int nt = 0; nt < 4; ++nt) {
            int c = nw + nt * 8 + lm * 2;
            gv0[nt] = __ldg(g2 + c);  gv1[nt] = __ldg(g2 + c + 1);
            ev0[nt] = __ldg(be2 + c); ev1[nt] = __ldg(be2 + c + 1);
        }
#pragma unroll
        for (int mt = 0; mt < 4; ++mt) {
            int r0 = mt * 16 + l4, r1 = r0 + 8;
            float mu0 = st2[r0 * 2] * (1.0f / 128.0f);
            float va0 = st2[r0 * 2 + 1] * (1.0f / 128.0f) - mu0 * mu0;
            float rs0 = rsqrtf(va0 + 1e-5f);
            float mu1 = st2[r1 * 2] * (1.0f / 128.0f);
            float va1 = st2[r1 * 2 + 1] * (1.0f / 128.0f) - mu1 * mu1;
            float rs1 = rsqrtf(va1 + 1e-5f);
            int s0i = sidx[r0], s1i = sidx[r1];
#pragma unroll
            for (int nt = 0; nt < 4; ++nt) {
                int c = nw + nt * 8 + lm * 2;
                if (s0i >= 0) {
                    float* dp = g_sum + (long)s0i * HID + c;
                    atomicAdd(dp,     fmaxf((acc[mt][nt][0] - mu0) * rs0 * gv0[nt] + ev0[nt], 0.f));
                    atomicAdd(dp + 1, fmaxf((acc[mt][nt][1] - mu0) * rs0 * gv1[nt] + ev1[nt], 0.f));
                }
                if (s1i >= 0) {
                    float* dp = g_sum + (long)s1i * HID + c;
                    atomicAdd(dp,     fmaxf((acc[mt][nt][2] - mu1) * rs1 * gv0[nt] + ev0[nt], 0.f));
                    atomicAdd(dp + 1, fmaxf((acc[mt][nt][3] - mu1) * rs1 * gv1[nt] + ev1[nt], 0.f));
                }
            }
        }
    }
    if (tid < 64 && sidx[tid] >= 0) atomicAdd(&g_cnt[sidx[tid]], 1.0f);
}

// ---------------- kernel 2a: GRU gate pre-activations via tf32 MMA ----------------
// 32 nodes/block, 128 threads = 4 warps; warp w owns gate-cols [w*96, w*96+96).
// Phase A: aggr @ WihT -> g_gx. Phase B: hprev @ WhhT -> g_gh (acc regs reused).
__global__ void __launch_bounds__(128) gru_gemm_k(const float* __restrict__ hprev)
{
    __shared__ float buf[32 * GSTR];   // 16.9 KB A tile

    const int tid  = threadIdx.x;
    const int w    = tid >> 5;
    const int lane = tid & 31;
    const int l4   = lane >> 2;
    const int lm   = lane & 3;
    const long base = (long)blockIdx.x * 32;
    const int nw   = w * 96;           // warp's first gate column

    float acc[2][12][4];

    // ---- phase A: stage aggr (scatter-mean, tf32) ----
    for (int idx = tid; idx < 32 * 32; idx += 128) {
        int e = idx >> 5, q = idx & 31;        // node row, float4 col
        long node = base + e;
        float4 v = make_float4(0.f, 0.f, 0.f, 0.f);
        if (node < N_NODES) {
            float c = fmaxf(g_cnt[node], 1.0f);
            v = ldg4(g_sum + node * HID + q * 4);
            v.x /= c; v.y /= c; v.z /= c; v.w /= c;
        }
        *(float4*)&buf[e * GSTR + q * 4] =
            make_float4(tf32f(v.x), tf32f(v.y), tf32f(v.z), tf32f(v.w));
    }
    __syncthreads();

#pragma unroll
    for (int mt = 0; mt < 2; ++mt)
#pragma unroll
        for (int nt = 0; nt < 12; ++nt)
#pragma unroll
            for (int i = 0; i < 4; ++i) acc[mt][nt][i] = 0.0f;

#pragma unroll 4
    for (int ks = 0; ks < 16; ++ks) {
        const int k0 = ks * 8;
        unsigned a[2][4];
#pragma unroll
        for (int mt = 0; mt < 2; ++mt) {
            const float* rp = buf + (mt * 16 + l4) * GSTR + k0 + lm;
            a[mt][0] = __float_as_uint(rp[0]);
            a[mt][1] = __float_as_uint(rp[8 * GSTR]);
            a[mt][2] = __float_as_uint(rp[4]);
            a[mt][3] = __float_as_uint(rp[8 * GSTR + 4]);
        }
#pragma unroll
        for (int nt = 0; nt < 12; ++nt) {
            int n = nw + nt * 8 + l4;
            unsigned b0 = __ldg(g_wihTtf + (k0 + lm) * 384 + n);
            unsigned b1 = __ldg(g_wihTtf + (k0 + lm + 4) * 384 + n);
#pragma unroll
            for (int mt = 0; mt < 2; ++mt)
                mma_tf32(acc[mt][nt], a[mt][0], a[mt][1], a[mt][2], a[mt][3], b0, b1);
        }
    }

    // store gx
#pragma unroll
    for (int mt = 0; mt < 2; ++mt) {
        long r0 = base + mt * 16 + l4, r1 = r0 + 8;
#pragma unroll
        for (int nt = 0; nt < 12; ++nt) {
            int n = nw + nt * 8 + lm * 2;
            if (r0 < N_NODES) *(float2*)&g_gx[r0 * 384 + n] = make_float2(acc[mt][nt][0], acc[mt][nt][1]);
            if (r1 < N_NODES) *(float2*)&g_gx[r1 * 384 + n] = make_float2(acc[mt][nt][2], acc[mt][nt][3]);
        }
    }
    __syncthreads();

    // ---- phase B: stage hprev (tf32) ----
    for (int idx = tid; idx < 32 * 32; idx += 128) {
        int e = idx >> 5, q = idx & 31;
        long node = base + e;
        float4 v = make_float4(0.f, 0.f, 0.f, 0.f);
        if (node < N_NODES) v = ldg4(hprev + node * HID + q * 4);
        *(float4*)&buf[e * GSTR + q * 4] =
            make_float4(tf32f(v.x), tf32f(v.y), tf32f(v.z), tf32f(v.w));
    }
    __syncthreads();

#pragma unroll
    for (int mt = 0; mt < 2; ++mt)
#pragma unroll
        for (int nt = 0; nt < 12; ++nt)
#pragma unroll
            for (int i = 0; i < 4; ++i) acc[mt][nt][i] = 0.0f;

#pragma unroll 4
    for (int ks = 0; ks < 16; ++ks) {
        const int k0 = ks * 8;
        unsigned a[2][4];
#pragma unroll
        for (int mt = 0; mt < 2; ++mt) {
            const float* rp = buf + (mt * 16 + l4) * GSTR + k0 + lm;
            a[mt][0] = __float_as_uint(rp[0]);
            a[mt][1] = __float_as_uint(rp[8 * GSTR]);
            a[mt][2] = __float_as_uint(rp[4]);
            a[mt][3] = __float_as_uint(rp[8 * GSTR + 4]);
        }
#pragma unroll
        for (int nt = 0; nt < 12; ++nt) {
            int n = nw + nt * 8 + l4;
            unsigned b0 = __ldg(g_whhTtf + (k0 + lm) * 384 + n);
            unsigned b1 = __ldg(g_whhTtf + (k0 + lm + 4) * 384 + n);
#pragma unroll
            for (int mt = 0; mt < 2; ++mt)
                mma_tf32(acc[mt][nt], a[mt][0], a[mt][1], a[mt][2], a[mt][3], b0, b1);
        }
    }

    // store gh
#pragma unroll
    for (int mt = 0; mt < 2; ++mt) {
        long r0 = base + mt * 16 + l4, r1 = r0 + 8;
#pragma unroll
        for (int nt = 0; nt < 12; ++nt) {
            int n = nw + nt * 8 + lm * 2;
            if (r0 < N_NODES) *(float2*)&g_gh[r0 * 384 + n] = make_float2(acc[mt][nt][0], acc[mt][nt][1]);
            if (r1 < N_NODES) *(float2*)&g_gh[r1 * 384 + n] = make_float2(acc[mt][nt][2], acc[mt][nt][3]);
        }
    }
}

// ---------------- kernel 2b: GRU gate nonlinearity -> g_hnew ----------------------
__global__ void __launch_bounds__(256) gru_gate_k(
    const float* __restrict__ hprev,
    const float* __restrict__ bih, const float* __restrict__ bhh)
{
    int i = blockIdx.x * 256 + threadIdx.x;   // over N_NODES*HID (exact multiple)
    int jj = i & 127;
    long b = (long)(i >> 7) * 384;
    float r = 1.0f / (1.0f + expf(-(g_gx[b + jj]       + __ldg(bih + jj)
                                  + g_gh[b + jj]       + __ldg(bhh + jj))));
    float z = 1.0f / (1.0f + expf(-(g_gx[b + 128 + jj] + __ldg(bih + 128 + jj)
                                  + g_gh[b + 128 + jj] + __ldg(bhh + 128 + jj))));
    float n = tanhf((g_gx[b + 256 + jj] + __ldg(bih + 256 + jj))
                    + r * (g_gh[b + 256 + jj] + __ldg(bhh + 256 + jj)));
    float hp = hprev[i];
    g_hnew[i] = (1.0f - z) * n + z * hp;
}

// ---------------- kernel 3: classifier, split-K tf32 mma (unchanged) --------------
__global__ void __launch_bounds__(128, 5) cls_k(
    const float* __restrict__ ea, const int* __restrict__ eidx,
    const float* __restrict__ bc1, const float* __restrict__ Wc2,
    const float* __restrict__ bc2, float* __restrict__ out)
{
    __shared__ float buf[64 * CSTR];
    __shared__ float part[64];

    const int tid  = threadIdx.x;
    const int w    = tid >> 5;
    const int lane = tid & 31;
    const int l4   = lane >> 2;
    const int lm   = lane & 3;
    const long base = (long)blockIdx.x * 64;
    const int nw   = w * 32;

    if (tid < 64) part[tid] = 0.0f;

    float acc[4][4][4];
#pragma unroll
    for (int mt = 0; mt < 4; ++mt)
#pragma unroll
        for (int nt = 0; nt < 4; ++nt)
#pragma unroll
            for (int i = 0; i < 4; ++i) acc[mt][nt][i] = 0.0f;

    for (int idx = tid; idx < 64 * 32; idx += 128) {
        int e = idx >> 5, q = idx & 31;
        long eg = base + e;
        float4 v = make_float4(0.f, 0.f, 0.f, 0.f);
        if (eg < N_EDGES) {
            int s = eidx[eg];
            v = ldg4(g_hnew + (long)s * HID + q * 4);
        }
        float4 t = make_float4(tf32f(v.x), tf32f(v.y), tf32f(v.z), tf32f(v.w));
        *(float4*)&buf[e * CSTR + q * 4] = t;
    }
    __syncthreads();

#pragma unroll 4
    for (int ks = 0; ks < 16; ++ks) {
        const int k0 = ks * 8;
        unsigned a[4][4];
#pragma unroll
        for (int mt = 0; mt < 4; ++mt) {
            const float* rp = buf + (mt * 16 + l4) * CSTR + k0 + lm;
            a[mt][0] = __float_as_uint(rp[0]);
            a[mt][1] = __float_as_uint(rp[8 * CSTR]);
            a[mt][2] = __float_as_uint(rp[4]);
            a[mt][3] = __float_as_uint(rp[8 * CSTR + 4]);
        }
#pragma unroll
        for (int nt = 0; nt < 4; ++nt) {
            int n = nw + nt * 8 + l4;
            unsigned b0 = __ldg(g_wtf + (k0 + lm) * HID + n);
            unsigned b1 = __ldg(g_wtf + (k0 + lm + 4) * HID + n);
#pragma unroll
            for (int mt = 0; mt < 4; ++mt)
                mma_tf32(acc[mt][nt], a[mt][0], a[mt][1], a[mt][2], a[mt][3], b0, b1);
        }
    }
    __syncthreads();

    for (int idx = tid; idx < 64 * 40; idx += 128) {
        int e = idx / 40, q = idx - e * 40;
        long eg = base + e;
        float4 v = make_float4(0.f, 0.f, 0.f, 0.f);
        if (eg < N_EDGES) {
            if (q < 32) {
                int d = eidx[N_EDGES + eg];
                v = ldg4(g_hnew + (long)d * HID + q * 4);
            } else {
                v = ldg4(ea + eg * EDIM + (q - 32) * 4);
            }
        }
        float4 t = make_float4(tf32f(v.x), tf32f(v.y), tf32f(v.z), tf32f(v.w));
        *(float4*)&buf[e * CSTR + q * 4] = t;
    }
    __syncthreads();

#pragma unroll 4
    for (int ks = 0; ks < 20; ++ks) {
        const int k0l = ks * 8;
        const int k0g = 128 + ks * 8;
        unsigned a[4][4];
#pragma unroll
        for (int mt = 0; mt < 4; ++mt) {
            const float* rp = buf + (mt * 16 + l4) * CSTR + k0l + lm;
            a[mt][0] = __float_as_uint(rp[0]);
            a[mt][1] = __float_as_uint(rp[8 * CSTR]);
            a[mt][2] = __float_as_uint(rp[4]);
            a[mt][3] = __float_as_uint(rp[8 * CSTR + 4]);
        }
#pragma unroll
        for (int nt = 0; nt < 4; ++nt) {
            int n = nw + nt * 8 + l4;
            unsigned b0 = __ldg(g_wtf + (k0g + lm) * HID + n);
            unsigned b1 = __ldg(g_wtf + (k0g + lm + 4) * HID + n);
#pragma unroll
            for (int mt = 0; mt < 4; ++mt)
                mma_tf32(acc[mt][nt], a[mt][0], a[mt][1], a[mt][2], a[mt][3], b0, b1);
        }
    }

#pragma unroll
    for (int nt = 0; nt < 4; ++nt) {
        int n0 = nw + nt * 8 + lm * 2;
        float bcA = __ldg(bc1 + n0),  float_bcB = 0.f;
        float bcB = __ldg(bc1 + n0 + 1);
        (void)float_bcB;
        float w2A = __ldg(Wc2 + n0),  w2B = __ldg(Wc2 + n0 + 1);
#pragma unroll
        for (int mt = 0; mt < 4; ++mt) {
            float vlo = fmaxf(acc[mt][nt][0] + bcA, 0.f) * w2A
                      + fmaxf(acc[mt][nt][1] + bcB, 0.f) * w2B;
            float vhi = fmaxf(acc[mt][nt][2] + bcA, 0.f) * w2A
                      + fmaxf(acc[mt][nt][3] + bcB, 0.f) * w2B;
            vlo += __shfl_xor_sync(0xffffffffu, vlo, 1);
            vlo += __shfl_xor_sync(0xffffffffu, vlo, 2);
            vhi += __shfl_xor_sync(0xffffffffu, vhi, 1);
            vhi += __shfl_xor_sync(0xffffffffu, vhi, 2);
            if (lm == 0) {
                atomicAdd(&part[mt * 16 + l4],     vlo);
                atomicAdd(&part[mt * 16 + l4 + 8], vhi);
            }
        }
    }
    __syncthreads();

    if (tid < 64) {
        long eg = base + tid;
        if (eg < N_EDGES) out[eg] = part[tid] + __ldg(bc2);
    }
}

// ---------------- launch ----------------
extern "C" void kernel_launch(void* const* d_in, const int* in_sizes, int n_in,
                              void* d_out, int out_size)
{
    (void)in_sizes; (void)n_in; (void)out_size;
    const int*   eidx  = (const int*)  d_in[1];
    const float* ea    = (const float*)d_in[2];
    const float* hprev = (const float*)d_in[3];
    const float* W1 = (const float*)d_in[4];
    const float* b1 = (const float*)d_in[5];
    const float* g1 = (const float*)d_in[6];
    const float* be1= (const float*)d_in[7];
    const float* W2 = (const float*)d_in[8];
    const float* b2 = (const float*)d_in[9];
    const float* g2 = (const float*)d_in[10];
    const float* be2= (const float*)d_in[11];
    const float* Wih= (const float*)d_in[12];
    const float* bih= (const float*)d_in[13];
    const float* Whh= (const float*)d_in[14];
    const float* bhh= (const float*)d_in[15];
    const float* Wc1= (const float*)d_in[16];
    const float* bc1= (const float*)d_in[17];
    const float* Wc2= (const float*)d_in[18];
    const float* bc2= (const float*)d_in[19];
    float* out = (float*)d_out;

    const int nblk = (N_EDGES + 63) / 64;
    zero_k<<<(N_NODES * HID + 255) / 256, 256>>>();
    prep_all_k<<<(KTOT * HID + 255) / 256, 256>>>(Wc1, W1, W2);
    prep_gruT_k<<<(HID * 384 + 255) / 256, 256>>>(Wih, Whh);
    enc_mma_k<<<nblk, 128>>>(ea, eidx, b1, g1, be1, b2, g2, be2);
    gru_gemm_k<<<(N_NODES + 31) / 32, 128>>>(hprev);
    gru_gate_k<<<(N_NODES * HID) / 256, 256>>>(hprev, bih, bhh);
    cls_k<<<nblk, 128>>>(ea, eidx, bc1, Wc2, bc2, out);
}

// round 16
// speedup vs baseline: 1.3563x; 1.1207x over previous
#include <cuda_runtime.h>

#define N_NODES 50000
#define N_EDGES 500000
#define HID 128
#define EDIM 32
#define KTOT (2 * HID + EDIM)   // 288
#define S2STR 132               // enc smem row stride (132 % 32 = 4)
#define CSTR 164                // cls smem row stride (164 % 32 = 4)
#define GSTR 132                // gru smem row stride

typedef unsigned long long u64;

// ---------------- scratch (device globals: no allocation allowed) ----------------
__device__ float    g_sum [N_NODES * HID];
__device__ float    g_cnt [N_NODES];
__device__ float    g_hnew[N_NODES * HID];
__device__ float    g_gx  [N_NODES * 384];    // GRU input-gate pre-activations
__device__ float    g_gh  [N_NODES * 384];    // GRU hidden-gate pre-activations
__device__ unsigned g_wtf [KTOT * HID];       // Wc1 tf32
__device__ unsigned g_w1tf[EDIM * HID];       // W1  tf32
__device__ unsigned g_w2tf[HID * HID];        // W2  tf32
__device__ unsigned g_wihTtf[HID * 384];      // Wih^T tf32 [k][j]
__device__ unsigned g_whhTtf[HID * 384];      // Whh^T tf32 [k][j]

// ---------------- zero scratch ----------------
__global__ void zero_k() {
    int i = blockIdx.x * blockDim.x + threadIdx.x;
    if (i < N_NODES * HID) g_sum[i] = 0.0f;
    if (i < N_NODES)       g_cnt[i] = 0.0f;
}

// ---------------- tf32 helpers ----------------
__device__ __forceinline__ unsigned f2tf(float x) {
    unsigned r;
    asm("cvt.rna.tf32.f32 %0, %1;" : "=r"(r) : "f"(x));
    return r;
}
__device__ __forceinline__ float tf32f(float x) { return __uint_as_float(f2tf(x)); }

__global__ void prep_all_k(const float* __restrict__ Wc1,
                           const float* __restrict__ W1,
                           const float* __restrict__ W2) {
    int i = blockIdx.x * blockDim.x + threadIdx.x;
    if (i < KTOT * HID) g_wtf [i] = f2tf(Wc1[i]);
    if (i < EDIM * HID) g_w1tf[i] = f2tf(W1[i]);
    if (i < HID  * HID) g_w2tf[i] = f2tf(W2[i]);
}

// transpose GRU weights to [k][j] tf32
__global__ void prep_gruT_k(const float* __restrict__ Wih, const float* __restrict__ Whh) {
    int i = blockIdx.x * blockDim.x + threadIdx.x;   // over 128*384
    if (i < HID * 384) {
        int k = i / 384, j = i - k * 384;
        g_wihTtf[i] = f2tf(Wih[(long)j * HID + k]);
        g_whhTtf[i] = f2tf(Whh[(long)j * HID + k]);
    }
}

__device__ __forceinline__ void mma_tf32(float* d,
                                         unsigned a0, unsigned a1, unsigned a2, unsigned a3,
                                         unsigned b0, unsigned b1) {
    asm("mma.sync.aligned.m16n8k8.row.col.f32.tf32.tf32.f32 "
        "{%0,%1,%2,%3}, {%4,%5,%6,%7}, {%8,%9}, {%0,%1,%2,%3};"
        : "+f"(d[0]), "+f"(d[1]), "+f"(d[2]), "+f"(d[3])
        : "r"(a0), "r"(a1), "r"(a2), "r"(a3), "r"(b0), "r"(b1));
}

__device__ __forceinline__ float4 ldg4(const float* p) { return __ldg((const float4*)p); }

// ---------------- kernel 1: edge encoder via tf32 MMA (unchanged) ----------------
__global__ void __launch_bounds__(128, 4) enc_mma_k(
    const float* __restrict__ ea, const int* __restrict__ eidx,
    const float* __restrict__ b1, const float* __restrict__ g1,
    const float* __restrict__ be1,
    const float* __restrict__ b2, const float* __restrict__ g2,
    const float* __restrict__ be2)
{
    __shared__ float buf[64 * S2STR];
    __shared__ float st1[64 * 2];
    __shared__ float st2[64 * 2];
    __shared__ int   sidx[64];

    const int tid  = threadIdx.x;
    const int w    = tid >> 5;
    const int lane = tid & 31;
    const int l4   = lane >> 2;
    const int lm   = lane & 3;
    const long base = (long)blockIdx.x * 64;
    const int nw   = w * 32;

    if (tid < 64) {
        st1[tid * 2] = 0.f; st1[tid * 2 + 1] = 0.f;
        st2[tid * 2] = 0.f; st2[tid * 2 + 1] = 0.f;
        long eg = base + tid;
        sidx[tid] = (eg < N_EDGES) ? eidx[eg] : -1;
    }
    for (int idx = tid; idx < 64 * 8; idx += 128) {
        int e = idx >> 3, q = idx & 7;
        long eg = base + e;
        float4 v = make_float4(0.f, 0.f, 0.f, 0.f);
        if (eg < N_EDGES) v = ldg4(ea + eg * EDIM + q * 4);
        float4 t = make_float4(tf32f(v.x), tf32f(v.y), tf32f(v.z), tf32f(v.w));
        *(float4*)&buf[e * S2STR + q * 4] = t;
    }
    __syncthreads();

    float acc[4][4][4];
#pragma unroll
    for (int mt = 0; mt < 4; ++mt)
#pragma unroll
        for (int nt = 0; nt < 4; ++nt)
#pragma unroll
            for (int i = 0; i < 4; ++i) acc[mt][nt][i] = 0.0f;

#pragma unroll
    for (int ks = 0; ks < 4; ++ks) {
        const int k0 = ks * 8;
        unsigned a[4][4];
#pragma unroll
        for (int mt = 0; mt < 4; ++mt) {
            const float* rp = buf + (mt * 16 + l4) * S2STR + k0 + lm;
            a[mt][0] = __float_as_uint(rp[0]);
            a[mt][1] = __float_as_uint(rp[8 * S2STR]);
            a[mt][2] = __float_as_uint(rp[4]);
            a[mt][3] = __float_as_uint(rp[8 * S2STR + 4]);
        }
#pragma unroll
        for (int nt = 0; nt < 4; ++nt) {
            int n = nw + nt * 8 + l4;
            unsigned bb0 = __ldg(g_w1tf + (k0 + lm) * HID + n);
            unsigned bb1 = __ldg(g_w1tf + (k0 + lm + 4) * HID + n);
#pragma unroll
            for (int mt = 0; mt < 4; ++mt)
                mma_tf32(acc[mt][nt], a[mt][0], a[mt][1], a[mt][2], a[mt][3], bb0, bb1);
        }
    }
    __syncthreads();

    {
        float bv0[4], bv1[4];
#pragma unroll
        for (int nt = 0; nt < 4; ++nt) {
            int c = nw + nt * 8 + lm * 2;
            bv0[nt] = __ldg(b1 + c); bv1[nt] = __ldg(b1 + c + 1);
        }
#pragma unroll
        for (int mt = 0; mt < 4; ++mt) {
            float s0 = 0.f, q0 = 0.f, s1 = 0.f, q1 = 0.f;
#pragma unroll
            for (int nt = 0; nt < 4; ++nt) {
                acc[mt][nt][0] += bv0[nt]; acc[mt][nt][1] += bv1[nt];
                acc[mt][nt][2] += bv0[nt]; acc[mt][nt][3] += bv1[nt];
                s0 += acc[mt][nt][0] + acc[mt][nt][1];
                q0 += acc[mt][nt][0] * acc[mt][nt][0] + acc[mt][nt][1] * acc[mt][nt][1];
                s1 += acc[mt][nt][2] + acc[mt][nt][3];
                q1 += acc[mt][nt][2] * acc[mt][nt][2] + acc[mt][nt][3] * acc[mt][nt][3];
            }
            s0 += __shfl_xor_sync(0xffffffffu, s0, 1); s0 += __shfl_xor_sync(0xffffffffu, s0, 2);
            q0 += __shfl_xor_sync(0xffffffffu, q0, 1); q0 += __shfl_xor_sync(0xffffffffu, q0, 2);
            s1 += __shfl_xor_sync(0xffffffffu, s1, 1); s1 += __shfl_xor_sync(0xffffffffu, s1, 2);
            q1 += __shfl_xor_sync(0xffffffffu, q1, 1); q1 += __shfl_xor_sync(0xffffffffu, q1, 2);
            if (lm == 0) {
                int r0 = mt * 16 + l4;
                atomicAdd(&st1[r0 * 2],  s0); atomicAdd(&st1[r0 * 2 + 1],  q0);
                atomicAdd(&st1[(r0 + 8) * 2], s1); atomicAdd(&st1[(r0 + 8) * 2 + 1], q1);
            }
        }
    }
    __syncthreads();

    {
        float gv0[4], gv1[4], ev0[4], ev1[4];
#pragma unroll
        for (int nt = 0; nt < 4; ++nt) {
            int c = nw + nt * 8 + lm * 2;
            gv0[nt] = __ldg(g1 + c);  gv1[nt] = __ldg(g1 + c + 1);
            ev0[nt] = __ldg(be1 + c); ev1[nt] = __ldg(be1 + c + 1);
        }
#pragma unroll
        for (int mt = 0; mt < 4; ++mt) {
            int r0 = mt * 16 + l4, r1 = r0 + 8;
            float mu0 = st1[r0 * 2] * (1.0f / 128.0f);
            float va0 = st1[r0 * 2 + 1] * (1.0f / 128.0f) - mu0 * mu0;
            float rs0 = rsqrtf(va0 + 1e-5f);
            float mu1 = st1[r1 * 2] * (1.0f / 128.0f);
            float va1 = st1[r1 * 2 + 1] * (1.0f / 128.0f) - mu1 * mu1;
            float rs1 = rsqrtf(va1 + 1e-5f);
#pragma unroll
            for (int nt = 0; nt < 4; ++nt) {
                int c = nw + nt * 8 + lm * 2;
                buf[r0 * S2STR + c]     = tf32f(fmaxf((acc[mt][nt][0] - mu0) * rs0 * gv0[nt] + ev0[nt], 0.f));
                buf[r0 * S2STR + c + 1] = tf32f(fmaxf((acc[mt][nt][1] - mu0) * rs0 * gv1[nt] + ev1[nt], 0.f));
                buf[r1 * S2STR + c]     = tf32f(fmaxf((acc[mt][nt][2] - mu1) * rs1 * gv0[nt] + ev0[nt], 0.f));
                buf[r1 * S2STR + c + 1] = tf32f(fmaxf((acc[mt][nt][3] - mu1) * rs1 * gv1[nt] + ev1[nt], 0.f));
            }
        }
    }
    __syncthreads();

#pragma unroll
    for (int mt = 0; mt < 4; ++mt)
#pragma unroll
        for (int nt = 0; nt < 4; ++nt)
#pragma unroll
            for (int i = 0; i < 4; ++i) acc[mt][nt][i] = 0.0f;

#pragma unroll 4
    for (int ks = 0; ks < 16; ++ks) {
        const int k0 = ks * 8;
        unsigned a[4][4];
#pragma unroll
        for (int mt = 0; mt < 4; ++mt) {
            const float* rp = buf + (mt * 16 + l4) * S2STR + k0 + lm;
            a[mt][0] = __float_as_uint(rp[0]);
            a[mt][1] = __float_as_uint(rp[8 * S2STR]);
            a[mt][2] = __float_as_uint(rp[4]);
            a[mt][3] = __float_as_uint(rp[8 * S2STR + 4]);
        }
#pragma unroll
        for (int nt = 0; nt < 4; ++nt) {
            int n = nw + nt * 8 + l4;
            unsigned bb0 = __ldg(g_w2tf + (k0 + lm) * HID + n);
            unsigned bb1 = __ldg(g_w2tf + (k0 + lm + 4) * HID + n);
#pragma unroll
            for (int mt = 0; mt < 4; ++mt)
                mma_tf32(acc[mt][nt], a[mt][0], a[mt][1], a[mt][2], a[mt][3], bb0, bb1);
        }
    }

    {
        float bv0[4], bv1[4];
#pragma unroll
        for (int nt = 0; nt < 4; ++nt) {
            int c = nw + nt * 8 + lm * 2;
            bv0[nt] = __ldg(b2 + c); bv1[nt] = __ldg(b2 + c + 1);
        }
#pragma unroll
        for (int mt = 0; mt < 4; ++mt) {
            float s0 = 0.f, q0 = 0.f, s1 = 0.f, q1 = 0.f;
#pragma unroll
            for (int nt = 0; nt < 4; ++nt) {
                acc[mt][nt][0] += bv0[nt]; acc[mt][nt][1] += bv1[nt];
                acc[mt][nt][2] += bv0[nt]; acc[mt][nt][3] += bv1[nt];
                s0 += acc[mt][nt][0] + acc[mt][nt][1];
                q0 += acc[mt][nt][0] * acc[mt][nt][0] + acc[mt][nt][1] * acc[mt][nt][1];
                s1 += acc[mt][nt][2] + acc[mt][nt][3];
                q1 += acc[mt][nt][2] * acc[mt][nt][2] + acc[mt][nt][3] * acc[mt][nt][3];
            }
            s0 += __shfl_xor_sync(0xffffffffu, s0, 1); s0 += __shfl_xor_sync(0xffffffffu, s0, 2);
            q0 += __shfl_xor_sync(0xffffffffu, q0, 1); q0 += __shfl_xor_sync(0xffffffffu, q0, 2);
            s1 += __shfl_xor_sync(0xffffffffu, s1, 1); s1 += __shfl_xor_sync(0xffffffffu, s1, 2);
            q1 += __shfl_xor_sync(0xffffffffu, q1, 1); q1 += __shfl_xor_sync(0xffffffffu, q1, 2);
            if (lm == 0) {
                int r0 = mt * 16 + l4;
                atomicAdd(&st2[r0 * 2],  s0); atomicAdd(&st2[r0 * 2 + 1],  q0);
                atomicAdd(&st2[(r0 + 8) * 2], s1); atomicAdd(&st2[(r0 + 8) * 2 + 1], q1);
            }
        }
    }
    __syncthreads();

    {
        float gv0[4], gv1[4], ev0[4], ev1[4];
#pragma unroll
        for (int nt = 0; nt < 4; ++nt) {
            int c = nw + nt * 8 + lm * 2;
            gv0[nt] = __ldg(g2 + c);  gv1[nt] = __ldg(g2 + c + 1);
            ev0[nt] = __ldg(be2 + c); ev1[nt] = __ldg(be2 + c + 1);
        }
#pragma unroll
        for (int mt = 0; mt < 4; ++mt) {
            int r0 = mt * 16 + l4, r1 = r0 + 8;
            float mu0 = st2[r0 * 2] * (1.0f / 128.0f);
            float va0 = st2[r0 * 2 + 1] * (1.0f / 128.0f) - mu0 * mu0;
            float rs0 = rsqrtf(va0 + 1e-5f);
            float mu1 = st2[r1 * 2] * (1.0f / 128.0f);
            float va1 = st2[r1 * 2 + 1] * (1.0f / 128.0f) - mu1 * mu1;
            float rs1 = rsqrtf(va1 + 1e-5f);
            int s0i = sidx[r0], s1i = sidx[r1];
#pragma unroll
            for (int nt = 0; nt < 4; ++nt) {
                int c = nw + nt * 8 + lm * 2;
                if (s0i >= 0) {
                    float* dp = g_sum + (long)s0i * HID + c;
                    atomicAdd(dp,     fmaxf((acc[mt][nt][0] - mu0) * rs0 * gv0[nt] + ev0[nt], 0.f));
                    atomicAdd(dp + 1, fmaxf((acc[mt][nt][1] - mu0) * rs0 * gv1[nt] + ev1[nt], 0.f));
                }
                if (s1i >= 0) {
                    float* dp = g_sum + (long)s1i * HID + c;
                    atomicAdd(dp,     fmaxf((acc[mt][nt][2] - mu1) * rs1 * gv0[nt] + ev0[nt], 0.f));
                    atomicAdd(dp + 1, fmaxf((acc[mt][nt][3] - mu1) * rs1 * gv1[nt] + ev1[nt], 0.f));
                }
            }
        }
    }
    if (tid < 64 && sidx[tid] >= 0) atomicAdd(&g_cnt[sidx[tid]], 1.0f);
}

// ---------------- kernel 2a: GRU gate pre-activations via tf32 MMA (unchanged) ----
__global__ void __launch_bounds__(128) gru_gemm_k(const float* __restrict__ hprev)
{
    __shared__ float buf[32 * GSTR];

    const int tid  = threadIdx.x;
    const int w    = tid >> 5;
    const int lane = tid & 31;
    const int l4   = lane >> 2;
    const int lm   = lane & 3;
    const long base = (long)blockIdx.x * 32;
    const int nw   = w * 96;

    float acc[2][12][4];

    for (int idx = tid; idx < 32 * 32; idx += 128) {
        int e = idx >> 5, q = idx & 31;
        long node = base + e;
        float4 v = make_float4(0.f, 0.f, 0.f, 0.f);
        if (node < N_NODES) {
            float c = fmaxf(g_cnt[node], 1.0f);
            v = ldg4(g_sum + node * HID + q * 4);
            v.x /= c; v.y /= c; v.z /= c; v.w /= c;
        }
        *(float4*)&buf[e * GSTR + q * 4] =
            make_float4(tf32f(v.x), tf32f(v.y), tf32f(v.z), tf32f(v.w));
    }
    __syncthreads();

#pragma unroll
    for (int mt = 0; mt < 2; ++mt)
#pragma unroll
        for (int nt = 0; nt < 12; ++nt)
#pragma unroll
            for (int i = 0; i < 4; ++i) acc[mt][nt][i] = 0.0f;

#pragma unroll 4
    for (int ks = 0; ks < 16; ++ks) {
        const int k0 = ks * 8;
        unsigned a[2][4];
#pragma unroll
        for (int mt = 0; mt < 2; ++mt) {
            const float* rp = buf + (mt * 16 + l4) * GSTR + k0 + lm;
            a[mt][0] = __float_as_uint(rp[0]);
            a[mt][1] = __float_as_uint(rp[8 * GSTR]);
            a[mt][2] = __float_as_uint(rp[4]);
            a[mt][3] = __float_as_uint(rp[8 * GSTR + 4]);
        }
#pragma unroll
        for (int nt = 0; nt < 12; ++nt) {
            int n = nw + nt * 8 + l4;
            unsigned b0 = __ldg(g_wihTtf + (k0 + lm) * 384 + n);
            unsigned b1 = __ldg(g_wihTtf + (k0 + lm + 4) * 384 + n);
#pragma unroll
            for (int mt = 0; mt < 2; ++mt)
                mma_tf32(acc[mt][nt], a[mt][0], a[mt][1], a[mt][2], a[mt][3], b0, b1);
        }
    }

#pragma unroll
    for (int mt = 0; mt < 2; ++mt) {
        long r0 = base + mt * 16 + l4, r1 = r0 + 8;
#pragma unroll
        for (int nt = 0; nt < 12; ++nt) {
            int n = nw + nt * 8 + lm * 2;
            if (r0 < N_NODES) *(float2*)&g_gx[r0 * 384 + n] = make_float2(acc[mt][nt][0], acc[mt][nt][1]);
            if (r1 < N_NODES) *(float2*)&g_gx[r1 * 384 + n] = make_float2(acc[mt][nt][2], acc[mt][nt][3]);
        }
    }
    __syncthreads();

    for (int idx = tid; idx < 32 * 32; idx += 128) {
        int e = idx >> 5, q = idx & 31;
        long node = base + e;
        float4 v = make_float4(0.f, 0.f, 0.f, 0.f);
        if (node < N_NODES) v = ldg4(hprev + node * HID + q * 4);
        *(float4*)&buf[e * GSTR + q * 4] =
            make_float4(tf32f(v.x), tf32f(v.y), tf32f(v.z), tf32f(v.w));
    }
    __syncthreads();

#pragma unroll
    for (int mt = 0; mt < 2; ++mt)
#pragma unroll
        for (int nt = 0; nt < 12; ++nt)
#pragma unroll
            for (int i = 0; i < 4; ++i) acc[mt][nt][i] = 0.0f;

#pragma unroll 4
    for (int ks = 0; ks < 16; ++ks) {
        const int k0 = ks * 8;
        unsigned a[2][4];
#pragma unroll
        for (int mt = 0; mt < 2; ++mt) {
            const float* rp = buf + (mt * 16 + l4) * GSTR + k0 + lm;
            a[mt][0] = __float_as_uint(rp[0]);
            a[mt][1] = __float_as_uint(rp[8 * GSTR]);
            a[mt][2] = __float_as_uint(rp[4]);
            a[mt][3] = __float_as_uint(rp[8 * GSTR + 4]);
        }
#pragma unroll
        for (int nt = 0; nt < 12; ++nt) {
            int n = nw + nt * 8 + l4;
            unsigned b0 = __ldg(g_whhTtf + (k0 + lm) * 384 + n);
            unsigned b1 = __ldg(g_whhTtf + (k0 + lm + 4) * 384 + n);
#pragma unroll
            for (int mt = 0; mt < 2; ++mt)
                mma_tf32(acc[mt][nt], a[mt][0], a[mt][1], a[mt][2], a[mt][3], b0, b1);
        }
    }

#pragma unroll
    for (int mt = 0; mt < 2; ++mt) {
        long r0 = base + mt * 16 + l4, r1 = r0 + 8;
#pragma unroll
        for (int nt = 0; nt < 12; ++nt) {
            int n = nw + nt * 8 + lm * 2;
            if (r0 < N_NODES) *(float2*)&g_gh[r0 * 384 + n] = make_float2(acc[mt][nt][0], acc[mt][nt][1]);
            if (r1 < N_NODES) *(float2*)&g_gh[r1 * 384 + n] = make_float2(acc[mt][nt][2], acc[mt][nt][3]);
        }
    }
}

// ---------------- kernel 2b: GRU gate nonlinearity (unchanged) --------------------
__global__ void __launch_bounds__(256) gru_gate_k(
    const float* __restrict__ hprev,
    const float* __restrict__ bih, const float* __restrict__ bhh)
{
    int i = blockIdx.x * 256 + threadIdx.x;
    int jj = i & 127;
    long b = (long)(i >> 7) * 384;
    float r = 1.0f / (1.0f + expf(-(g_gx[b + jj]       + __ldg(bih + jj)
                                  + g_gh[b + jj]       + __ldg(bhh + jj))));
    float z = 1.0f / (1.0f + expf(-(g_gx[b + 128 + jj] + __ldg(bih + 128 + jj)
                                  + g_gh[b + 128 + jj] + __ldg(bhh + 128 + jj))));
    float n = tanhf((g_gx[b + 256 + jj] + __ldg(bih + 256 + jj))
                    + r * (g_gh[b + 256 + jj] + __ldg(bhh + 256 + jj)));
    float hp = hprev[i];
    g_hnew[i] = (1.0f - z) * n + z * hp;
}

// ---------------- kernel 3: classifier, split-K tf32 mma, 8 warps x 16 cols -------
// 256 threads = 8 warps; warp w owns output cols [w*16, w*16+16) (nt=2).
// Same 64-edge M-tile, same per-accumulator K-order as before.
__global__ void __launch_bounds__(256, 3) cls_k(
    const float* __restrict__ ea, const int* __restrict__ eidx,
    const float* __restrict__ bc1, const float* __restrict__ Wc2,
    const float* __restrict__ bc2, float* __restrict__ out)
{
    __shared__ float buf[64 * CSTR];   // 42.0 KB
    __shared__ float part[64];

    const int tid  = threadIdx.x;
    const int w    = tid >> 5;         // 0..7
    const int lane = tid & 31;
    const int l4   = lane >> 2;
    const int lm   = lane & 3;
    const long base = (long)blockIdx.x * 64;
    const int nw   = w * 16;           // warp's first output column

    if (tid < 64) part[tid] = 0.0f;

    float acc[4][2][4];
#pragma unroll
    for (int mt = 0; mt < 4; ++mt)
#pragma unroll
        for (int nt = 0; nt < 2; ++nt)
#pragma unroll
            for (int i = 0; i < 4; ++i) acc[mt][nt][i] = 0.0f;

    // ---- phase A: gather h_src rows (128 cols) ----
    for (int idx = tid; idx < 64 * 32; idx += 256) {
        int e = idx >> 5, q = idx & 31;
        long eg = base + e;
        float4 v = make_float4(0.f, 0.f, 0.f, 0.f);
        if (eg < N_EDGES) {
            int s = eidx[eg];
            v = ldg4(g_hnew + (long)s * HID + q * 4);
        }
        float4 t = make_float4(tf32f(v.x), tf32f(v.y), tf32f(v.z), tf32f(v.w));
        *(float4*)&buf[e * CSTR + q * 4] = t;
    }
    __syncthreads();

#pragma unroll 4
    for (int ks = 0; ks < 16; ++ks) {
        const int k0 = ks * 8;
        unsigned a[4][4];
#pragma unroll
        for (int mt = 0; mt < 4; ++mt) {
            const float* rp = buf + (mt * 16 + l4) * CSTR + k0 + lm;
            a[mt][0] = __float_as_uint(rp[0]);
            a[mt][1] = __float_as_uint(rp[8 * CSTR]);
            a[mt][2] = __float_as_uint(rp[4]);
            a[mt][3] = __float_as_uint(rp[8 * CSTR + 4]);
        }
#pragma unroll
        for (int nt = 0; nt < 2; ++nt) {
            int n = nw + nt * 8 + l4;
            unsigned b0 = __ldg(g_wtf + (k0 + lm) * HID + n);
            unsigned b1 = __ldg(g_wtf + (k0 + lm + 4) * HID + n);
#pragma unroll
            for (int mt = 0; mt < 4; ++mt)
                mma_tf32(acc[mt][nt], a[mt][0], a[mt][1], a[mt][2], a[mt][3], b0, b1);
        }
    }
    __syncthreads();

    // ---- phase B: gather h_dst (cols 0..127) + edge_attr (cols 128..159) ----
    for (int idx = tid; idx < 64 * 40; idx += 256) {
        int e = idx / 40, q = idx - e * 40;
        long eg = base + e;
        float4 v = make_float4(0.f, 0.f, 0.f, 0.f);
        if (eg < N_EDGES) {
            if (q < 32) {
                int d = eidx[N_EDGES + eg];
                v = ldg4(g_hnew + (long)d * HID + q * 4);
            } else {
                v = ldg4(ea + eg * EDIM + (q - 32) * 4);
            }
        }
        float4 t = make_float4(tf32f(v.x), tf32f(v.y), tf32f(v.z), tf32f(v.w));
        *(float4*)&buf[e * CSTR + q * 4] = t;
    }
    __syncthreads();

#pragma unroll 4
    for (int ks = 0; ks < 20; ++ks) {
        const int k0l = ks * 8;
        const int k0g = 128 + ks * 8;
        unsigned a[4][4];
#pragma unroll
        for (int mt = 0; mt < 4; ++mt) {
            const float* rp = buf + (mt * 16 + l4) * CSTR + k0l + lm;
            a[mt][0] = __float_as_uint(rp[0]);
            a[mt][1] = __float_as_uint(rp[8 * CSTR]);
            a[mt][2] = __float_as_uint(rp[4]);
            a[mt][3] = __float_as_uint(rp[8 * CSTR + 4]);
        }
#pragma unroll
        for (int nt = 0; nt < 2; ++nt) {
            int n = nw + nt * 8 + l4;
            unsigned b0 = __ldg(g_wtf + (k0g + lm) * HID + n);
            unsigned b1 = __ldg(g_wtf + (k0g + lm + 4) * HID + n);
#pragma unroll
            for (int mt = 0; mt < 4; ++mt)
                mma_tf32(acc[mt][nt], a[mt][0], a[mt][1], a[mt][2], a[mt][3], b0, b1);
        }
    }

    // ---- epilogue: bias + ReLU + Wc2 dot + quad reduce + smem atomics ----
#pragma unroll
    for (int nt = 0; nt < 2; ++nt) {
        int n0 = nw + nt * 8 + lm * 2;
        float bcA = __ldg(bc1 + n0),  bcB = __ldg(bc1 + n0 + 1);
        float w2A = __ldg(Wc2 + n0),  w2B = __ldg(Wc2 + n0 + 1);
#pragma unroll
        for (int mt = 0; mt < 4; ++mt) {
            float vlo = fmaxf(acc[mt][nt][0] + bcA, 0.f) * w2A
                      + fmaxf(acc[mt][nt][1] + bcB, 0.f) * w2B;
            float vhi = fmaxf(acc[mt][nt][2] + bcA, 0.f) * w2A
                      + fmaxf(acc[mt][nt][3] + bcB, 0.f) * w2B;
            vlo += __shfl_xor_sync(0xffffffffu, vlo, 1);
            vlo += __shfl_xor_sync(0xffffffffu, vlo, 2);
            vhi += __shfl_xor_sync(0xffffffffu, vhi, 1);
            vhi += __shfl_xor_sync(0xffffffffu, vhi, 2);
            if (lm == 0) {
                atomicAdd(&part[mt * 16 + l4],     vlo);
                atomicAdd(&part[mt * 16 + l4 + 8], vhi);
            }
        }
    }
    __syncthreads();

    if (tid < 64) {
        long eg = base + tid;
        if (eg < N_EDGES) out[eg] = part[tid] + __ldg(bc2);
    }
}

// ---------------- launch ----------------
extern "C" void kernel_launch(void* const* d_in, const int* in_sizes, int n_in,
                              void* d_out, int out_size)
{
    (void)in_sizes; (void)n_in; (void)out_size;
    const int*   eidx  = (const int*)  d_in[1];
    const float* ea    = (const float*)d_in[2];
    const float* hprev = (const float*)d_in[3];
    const float* W1 = (const float*)d_in[4];
    const float* b1 = (const float*)d_in[5];
    const float* g1 = (const float*)d_in[6];
    const float* be1= (const float*)d_in[7];
    const float* W2 = (const float*)d_in[8];
    const float* b2 = (const float*)d_in[9];
    const float* g2 = (const float*)d_in[10];
    const float* be2= (const float*)d_in[11];
    const float* Wih= (const float*)d_in[12];
    const float* bih= (const float*)d_in[13];
    const float* Whh= (const float*)d_in[14];
    const float* bhh= (const float*)d_in[15];
    const float* Wc1= (const float*)d_in[16];
    const float* bc1= (const float*)d_in[17];
    const float* Wc2= (const float*)d_in[18];
    const float* bc2= (const float*)d_in[19];
    float* out = (float*)d_out;

    const int nblk = (N_EDGES + 63) / 64;
    zero_k<<<(N_NODES * HID + 255) / 256, 256>>>();
    prep_all_k<<<(KTOT * HID + 255) / 256, 256>>>(Wc1, W1, W2);
    prep_gruT_k<<<(HID * 384 + 255) / 256, 256>>>(Wih, Whh);
    enc_mma_k<<<nblk, 128>>>(ea, eidx, b1, g1, be1, b2, g2, be2);
    gru_gemm_k<<<(N_NODES + 31) / 32, 128>>>(hprev);
    gru_gate_k<<<(N_NODES * HID) / 256, 256>>>(hprev, bih, bhh);
    cls_k<<<nblk, 256>>>(ea, eidx, bc1, Wc2, bc2, out);
}